// round 5
// baseline (speedup 1.0000x reference)
#include <cuda_runtime.h>
#include <cuda_bf16.h>
#include <cstdint>
#include <cstddef>

// CombineGraph: h = emb[inputs]; e_k = leakyrelu(einsum(bid,bjd,d->bij; h,h,a_k));
// alpha = softmax(select_by_adj(e_k, -9e15)); out = alpha @ h.
// B=512, L=100, D=128. 4 CTAs per batch (i-row split, 26 rows each), 2 CTA/SM.
// GEMM1: bf16 m16n8k16 with A pre-scaled by all 4 a_k, interleaved so one LDS.128
// fetches A-regs for all edge types (2.0 issue slots/mma). GEMM2: tf32 mma.sync.

#define B_    512
#define L_    100
#define D_    128
#define AS    108        // alpha row stride (floats)
#define ADJS  104        // adj row stride (bytes)
#define NEG_INF_ -9e15f

// ---- smem byte offsets ----
#define OFF_H    0            // h f32 swizzled: 104*128*4 = 53248
#define OFF_HB   53248        // h bf16x2 swizzled: 104*64*4 = 26624 (al overlays after GEMM1)
#define OFF_HAM  79872        // ham uint4: 28*64*16 = 28672
#define OFF_ADJ  108544       // adj int8: 26*104 = 2704
#define OFF_ATP  111248       // a packed uint4[64] = 1024
#define SMEM_TOTAL 112272

// swizzled word indices (conflict-free for both write and mma-fragment read patterns)
#define HW(r, c)    ((r) * 128 + ((c) ^ (((r) & 3) << 3)))      // h f32 (float idx)
#define HBW(r, wd)  ((r) * 64 + ((wd) ^ (((r) & 7) << 2)))      // hb (u32 idx)
#define HAMW(r, wd) ((r) * 64 + ((wd) ^ (((r) & 1) << 2)))      // ham (uint4 idx)

__device__ __forceinline__ float rna_tf32(float x) {
    unsigned u; asm("cvt.rna.tf32.f32 %0, %1;" : "=r"(u) : "f"(x));
    return __uint_as_float(u);
}
__device__ __forceinline__ unsigned pack_bf16x2(float lo, float hi) {
    unsigned r; asm("cvt.rn.satfinite.bf16x2.f32 %0, %1, %2;" : "=r"(r) : "f"(hi), "f"(lo));
    return r;
}
__device__ __forceinline__ unsigned mulbf2(unsigned a, unsigned b) {
    unsigned r; asm("mul.bf16x2 %0, %1, %2;" : "=r"(r) : "r"(a), "r"(b));
    return r;
}
__device__ __forceinline__ void mma_bf16(float* c, unsigned a0, unsigned a1,
                                         unsigned a2, unsigned a3,
                                         unsigned b0, unsigned b1) {
    asm volatile(
        "mma.sync.aligned.m16n8k16.row.col.f32.bf16.bf16.f32 "
        "{%0,%1,%2,%3},{%4,%5,%6,%7},{%8,%9},{%0,%1,%2,%3};\n"
        : "+f"(c[0]), "+f"(c[1]), "+f"(c[2]), "+f"(c[3])
        : "r"(a0), "r"(a1), "r"(a2), "r"(a3), "r"(b0), "r"(b1));
}
__device__ __forceinline__ void mma_tf32(float* c, const unsigned* a, unsigned b0, unsigned b1) {
    asm volatile(
        "mma.sync.aligned.m16n8k8.row.col.f32.tf32.tf32.f32 "
        "{%0,%1,%2,%3},{%4,%5,%6,%7},{%8,%9},{%0,%1,%2,%3};\n"
        : "+f"(c[0]), "+f"(c[1]), "+f"(c[2]), "+f"(c[3])
        : "r"(a[0]), "r"(a[1]), "r"(a[2]), "r"(a[3]), "r"(b0), "r"(b1));
}

__global__ __launch_bounds__(512, 2)
void combine_graph_kernel(const int* __restrict__ inputs,
                          const int* __restrict__ adj,
                          const float* __restrict__ emb,
                          const float* __restrict__ a0p,
                          const float* __restrict__ a1p,
                          const float* __restrict__ a2p,
                          const float* __restrict__ a3p,
                          float* __restrict__ out)
{
    extern __shared__ char smem[];
    float*    h_sm   = (float*)(smem + OFF_H);
    unsigned* hb_sm  = (unsigned*)(smem + OFF_HB);
    float*    al_sm  = (float*)(smem + OFF_HB);    // overlays hb after GEMM1
    uint4*    ham4   = (uint4*)(smem + OFF_HAM);
    char*     adj_sm = smem + OFF_ADJ;
    uint4*    atp4   = (uint4*)(smem + OFF_ATP);

    const int b    = blockIdx.x >> 2;
    const int part = blockIdx.x & 3;
    const int i0   = part * 26;          // global i-row base for this CTA
    const int tid  = threadIdx.x;
    const int w    = tid >> 5;
    const int lane = tid & 31;
    const int g    = lane >> 2;
    const int t4   = lane & 3;

    const int* inp  = inputs + b * L_;
    const int* adjb = adj + (size_t)b * (L_ * L_);

    // ---------------- phase 0: loads ----------------
    if (tid < 256) {   // atp[wd] = {pack(a0), pack(a1), pack(a2), pack(a3)} for word wd
        int wd = tid & 63, k = tid >> 6;
        const float* ap = (k == 0) ? a0p : (k == 1) ? a1p : (k == 2) ? a2p : a3p;
        unsigned pk = pack_bf16x2(ap[2 * wd], ap[2 * wd + 1]);
        unsigned* dst = (unsigned*)(atp4 + wd);
        dst[k] = pk;
    }
    // embedding gather -> h f32 (tf32, swizzled) + hb bf16 (swizzled); rows 100..103 zero
    for (int e = tid; e < 104 * 32; e += 512) {
        int r = e >> 5, q = e & 31;
        float4 v = make_float4(0.f, 0.f, 0.f, 0.f);
        if (r < L_) {
            int id = inp[r];
            v = ((const float4*)(emb + (size_t)id * D_))[q];
            v.x = rna_tf32(v.x); v.y = rna_tf32(v.y);
            v.z = rna_tf32(v.z); v.w = rna_tf32(v.w);
        }
        *(float4*)(h_sm + HW(r, 4 * q)) = v;
        uint2 p2 = make_uint2(pack_bf16x2(v.x, v.y), pack_bf16x2(v.z, v.w));
        *(uint2*)(hb_sm + HBW(r, 2 * q)) = p2;
    }
    // adj (local 26 rows) -> int8
    for (int e = tid; e < 26 * 25; e += 512) {
        int lr = e / 25, c = e % 25;
        int gi = i0 + lr;
        unsigned p = 0u;
        if (gi < L_) {
            int4 v = ((const int4*)(adjb + gi * 100))[c];
            p = (unsigned)(v.x & 0xff) | ((unsigned)(v.y & 0xff) << 8)
              | ((unsigned)(v.z & 0xff) << 16) | ((unsigned)(v.w & 0xff) << 24);
        }
        *(unsigned*)(adj_sm + lr * ADJS + c * 4) = p;
    }
    __syncthreads();

    // ---------------- phase 0b: build ham (A pre-scaled by all 4 a_k) ----------------
    for (int e = tid; e < 28 * 64; e += 512) {
        int r = e >> 6, wd = e & 63;
        unsigned hbw = 0u;
        if (r < 26) hbw = hb_sm[HBW(i0 + r, wd)];   // rows >= 100 already zero
        uint4 at = atp4[wd];
        uint4 o;
        o.x = mulbf2(hbw, at.x); o.y = mulbf2(hbw, at.y);
        o.z = mulbf2(hbw, at.z); o.w = mulbf2(hbw, at.w);
        ham4[HAMW(r, wd)] = o;
    }
    __syncthreads();

    // ---------- phase 1: GEMM1 (bf16, A carries all 4 edge types via LDS.128) ----------
    unsigned stg[2][2];   // staged logits bf16x2 [nn][hf]
    stg[0][0] = stg[0][1] = stg[1][0] = stg[1][1] = 0;
    int r0 = 0, jc0 = 0, nnmax = 0;
    if (w < 14) {
        int mt = (w >= 7) ? 1 : 0;
        int np = w - 7 * mt;
        r0  = mt * 16;
        jc0 = np * 16;
        nnmax = (np == 6) ? 1 : 2;

        float c[2][4][4];
        #pragma unroll
        for (int nn = 0; nn < 2; ++nn)
            #pragma unroll
            for (int k = 0; k < 4; ++k)
                #pragma unroll
                for (int r = 0; r < 4; ++r) c[nn][k][r] = 0.f;

        const int ra = r0 + g, rb = r0 + 8 + g;
        const bool rbok = (rb < 28);
        const int swa = (g & 1) << 2;   // ham swizzle (ra&1 == rb&1 == g&1)
        const int swj = g << 2;         // hb swizzle for B rows (jr&7 == g)
        const uint4 z4 = make_uint4(0, 0, 0, 0);

        #pragma unroll 2
        for (int ks = 0; ks < 8; ++ks) {
            int wd0 = ks * 8 + t4;
            uint4 A0 = ham4[ra * 64 + (wd0 ^ swa)];
            uint4 A1 = rbok ? ham4[rb * 64 + (wd0 ^ swa)] : z4;
            uint4 A2 = ham4[ra * 64 + ((wd0 + 4) ^ swa)];
            uint4 A3 = rbok ? ham4[rb * 64 + ((wd0 + 4) ^ swa)] : z4;
            #pragma unroll
            for (int nn = 0; nn < 2; ++nn) {
                if (nn < nnmax) {
                    int jr = jc0 + nn * 8 + g;
                    unsigned B0 = hb_sm[jr * 64 + (wd0 ^ swj)];
                    unsigned B1 = hb_sm[jr * 64 + ((wd0 + 4) ^ swj)];
                    mma_bf16(c[nn][0], A0.x, A1.x, A2.x, A3.x, B0, B1);
                    mma_bf16(c[nn][1], A0.y, A1.y, A2.y, A3.y, B0, B1);
                    mma_bf16(c[nn][2], A0.z, A1.z, A2.z, A3.z, B0, B1);
                    mma_bf16(c[nn][3], A0.w, A1.w, A2.w, A3.w, B0, B1);
                }
            }
        }
        // select by adj + leaky-relu -> staged bf16x2
        #pragma unroll
        for (int nn = 0; nn < 2; ++nn) {
            #pragma unroll
            for (int hf = 0; hf < 2; ++hf) {
                int lrow = r0 + g + hf * 8;
                int grow = i0 + lrow;
                float v[2];
                #pragma unroll
                for (int e = 0; e < 2; ++e) {
                    int col = jc0 + nn * 8 + 2 * t4 + e;
                    int p = hf * 2 + e;
                    float val = NEG_INF_;
                    if (nn < nnmax && lrow < 26 && grow < L_ && col < L_) {
                        int t = adj_sm[lrow * ADJS + col];
                        float x = (t == 1) ? c[nn][0][p] :
                                  (t == 2) ? c[nn][1][p] :
                                  (t == 3) ? c[nn][2][p] : c[nn][3][p];
                        x = (x > 0.f) ? x : 0.2f * x;
                        val = t ? x : NEG_INF_;
                    }
                    v[e] = val;
                }
                stg[nn][hf] = pack_bf16x2(v[0], v[1]);
            }
        }
    }
    __syncthreads();   // hb dead; al overlay becomes valid

    // write staged logits to al (rows < 26 only) + zero pad rows 26..31
    if (w < 14) {
        #pragma unroll
        for (int nn = 0; nn < 2; ++nn) {
            if (nn < nnmax) {
                int col0 = jc0 + nn * 8 + 2 * t4;
                #pragma unroll
                for (int hf = 0; hf < 2; ++hf) {
                    int lrow = r0 + g + hf * 8;
                    if (lrow < 26) {
                        unsigned pk = stg[nn][hf];
                        float2 vv = make_float2(__uint_as_float(pk << 16),
                                                __uint_as_float(pk & 0xffff0000u));
                        *(float2*)(al_sm + lrow * AS + col0) = vv;
                    }
                }
            }
        }
    }
    for (int e = tid; e < 6 * AS; e += 512) al_sm[26 * AS + e] = 0.f;
    __syncthreads();

    // ---------------- phase 2: softmax over j (local rows 0..25) ----------------
    for (int i = w; i < 26; i += 16) {
        float x[4];
        #pragma unroll
        for (int q = 0; q < 4; ++q) {
            int j = lane + 32 * q;
            x[q] = (j < 104) ? al_sm[i * AS + j] : NEG_INF_;
        }
        float mx = fmaxf(fmaxf(x[0], x[1]), fmaxf(x[2], x[3]));
        #pragma unroll
        for (int o = 16; o > 0; o >>= 1) mx = fmaxf(mx, __shfl_xor_sync(0xffffffffu, mx, o));
        float ev[4], s = 0.f;
        #pragma unroll
        for (int q = 0; q < 4; ++q) {
            int j = lane + 32 * q;
            ev[q] = (j < L_) ? __expf(x[q] - mx) : 0.f;
            s += ev[q];
        }
        #pragma unroll
        for (int o = 16; o > 0; o >>= 1) s += __shfl_xor_sync(0xffffffffu, s, o);
        float inv = 1.f / s;
        #pragma unroll
        for (int q = 0; q < 4; ++q) {
            int j = lane + 32 * q;
            if (j < L_)       al_sm[i * AS + j] = rna_tf32(ev[q] * inv);
            else if (j < 104) al_sm[i * AS + j] = 0.f;
        }
    }
    __syncthreads();

    // ---------------- phase 3: GEMM2  out = alpha @ h  (tf32) ----------------
    {
        const int nt = w;   // one n8 tile per warp (16 x 8 = D=128)
        float c2[2][4];
        #pragma unroll
        for (int h = 0; h < 2; ++h)
            #pragma unroll
            for (int r = 0; r < 4; ++r) c2[h][r] = 0.f;

        #pragma unroll 4
        for (int kt = 0; kt < 13; ++kt) {
            int col = kt * 8 + t4;
            unsigned A2[2][4];
            #pragma unroll
            for (int h = 0; h < 2; ++h) {
                int r = h * 16 + g;
                A2[h][0] = __float_as_uint(al_sm[r * AS + col]);
                A2[h][1] = __float_as_uint(al_sm[(r + 8) * AS + col]);
                A2[h][2] = __float_as_uint(al_sm[r * AS + col + 4]);
                A2[h][3] = __float_as_uint(al_sm[(r + 8) * AS + col + 4]);
            }
            unsigned B0 = __float_as_uint(h_sm[HW(col, nt * 8 + g)]);
            unsigned B1 = __float_as_uint(h_sm[HW(col + 4, nt * 8 + g)]);
            mma_tf32(c2[0], A2[0], B0, B1);
            mma_tf32(c2[1], A2[1], B0, B1);
        }
        float* outb = out + (size_t)b * (L_ * D_);
        #pragma unroll
        for (int h = 0; h < 2; ++h) {
            #pragma unroll
            for (int p = 0; p < 2; ++p) {
                int lrow = h * 16 + g + p * 8;
                int grow = i0 + lrow;
                if (lrow < 26 && grow < L_) {
                    int colo = nt * 8 + t4 * 2;
                    float2 v2 = make_float2(c2[h][p * 2], c2[h][p * 2 + 1]);
                    *(float2*)(outb + grow * D_ + colo) = v2;
                }
            }
        }
    }
}

extern "C" void kernel_launch(void* const* d_in, const int* in_sizes, int n_in,
                              void* d_out, int out_size) {
    // metadata order: inputs, adj, mask_item, item, emb_table, a0, a1, a2, a3
    const int*   inputs = (const int*)d_in[0];
    const int*   adj    = (const int*)d_in[1];
    const float* emb    = (const float*)d_in[4];
    const float* a0     = (const float*)d_in[5];
    const float* a1     = (const float*)d_in[6];
    const float* a2     = (const float*)d_in[7];
    const float* a3     = (const float*)d_in[8];
    float* out = (float*)d_out;

    cudaFuncSetAttribute(combine_graph_kernel,
                         cudaFuncAttributeMaxDynamicSharedMemorySize, SMEM_TOTAL);

    combine_graph_kernel<<<B_ * 4, 512, SMEM_TOTAL>>>(inputs, adj, emb, a0, a1, a2, a3, out);
}

// round 6
// speedup vs baseline: 1.7066x; 1.7066x over previous
#include <cuda_runtime.h>
#include <cuda_bf16.h>
#include <cstdint>
#include <cstddef>

// CombineGraph: h = emb[inputs]; e_k = leakyrelu(einsum(bid,bjd,d->bij; h,h,a_k));
// alpha = softmax(select_by_adj(e_k, -9e15)); out = alpha @ h.
// B=512, L=100, D=128. One CTA/batch, 2 CTA/SM.
// GEMM1: bf16 m16n8k16, B scaled by packed a_k; hb pair-layout -> LDS.64 fragments,
// fully unrolled k-loops (immediate-offset LDS). GEMM2: tf32 mma.sync, swizzled h.

#define B_    512
#define L_    100
#define D_    128
#define HB    72         // hb row stride (u32 words), pair layout, conflict-free LDS.64
#define AS    108        // alpha row stride (floats)
#define ADJS  112        // adj row stride (bytes)
#define NEG_INF_ -9e15f

// ---- smem byte offsets ----
#define OFF_H    0            // h f32 swizzled: 104*128*4 = 53248
#define OFF_HB   53248        // h bf16 pair layout: 104*72*4 = 29952
#define OFF_ATP  83200        // a packed uint4[64] = 1024
#define OFF_ADJ  84224        // adj int8: 100*112 = 11200 (end 95424)
#define OFF_AL   53248        // alpha overlays hb/atp/adj: 104*108*4 = 44928 (end 98176)
#define SMEM_TOTAL 98176

// h f32 swizzle: conflict-free for STS.128 write and GEMM2 B-fragment read
#define HW(r, c) ((r) * 128 + ((c) ^ (((r) & 3) << 3)))

__device__ __forceinline__ float rna_tf32(float x) {
    unsigned u; asm("cvt.rna.tf32.f32 %0, %1;" : "=r"(u) : "f"(x));
    return __uint_as_float(u);
}
__device__ __forceinline__ unsigned pack_bf16x2(float lo, float hi) {
    unsigned r; asm("cvt.rn.satfinite.bf16x2.f32 %0, %1, %2;" : "=r"(r) : "f"(hi), "f"(lo));
    return r;
}
__device__ __forceinline__ unsigned mulbf2(unsigned a, unsigned b) {
    unsigned r; asm("mul.bf16x2 %0, %1, %2;" : "=r"(r) : "r"(a), "r"(b));
    return r;
}
__device__ __forceinline__ void mma_bf16(float* c, unsigned a0, unsigned a1,
                                         unsigned a2, unsigned a3,
                                         unsigned b0, unsigned b1) {
    asm volatile(
        "mma.sync.aligned.m16n8k16.row.col.f32.bf16.bf16.f32 "
        "{%0,%1,%2,%3},{%4,%5,%6,%7},{%8,%9},{%0,%1,%2,%3};\n"
        : "+f"(c[0]), "+f"(c[1]), "+f"(c[2]), "+f"(c[3])
        : "r"(a0), "r"(a1), "r"(a2), "r"(a3), "r"(b0), "r"(b1));
}
__device__ __forceinline__ void mma_tf32(float* c, const unsigned* a, unsigned b0, unsigned b1) {
    asm volatile(
        "mma.sync.aligned.m16n8k8.row.col.f32.tf32.tf32.f32 "
        "{%0,%1,%2,%3},{%4,%5,%6,%7},{%8,%9},{%0,%1,%2,%3};\n"
        : "+f"(c[0]), "+f"(c[1]), "+f"(c[2]), "+f"(c[3])
        : "r"(a[0]), "r"(a[1]), "r"(a[2]), "r"(a[3]), "r"(b0), "r"(b1));
}

__global__ __launch_bounds__(512, 2)
void combine_graph_kernel(const int* __restrict__ inputs,
                          const int* __restrict__ adj,
                          const float* __restrict__ emb,
                          const float* __restrict__ a0p,
                          const float* __restrict__ a1p,
                          const float* __restrict__ a2p,
                          const float* __restrict__ a3p,
                          float* __restrict__ out)
{
    extern __shared__ char smem[];
    float*    h_sm   = (float*)(smem + OFF_H);
    unsigned* hb_sm  = (unsigned*)(smem + OFF_HB);
    uint4*    atp4   = (uint4*)(smem + OFF_ATP);
    char*     adj_sm = smem + OFF_ADJ;
    float*    al_sm  = (float*)(smem + OFF_AL);   // overlays hb/atp/adj after GEMM1

    const int b    = blockIdx.x;
    const int tid  = threadIdx.x;
    const int w    = tid >> 5;
    const int lane = tid & 31;
    const int g    = lane >> 2;
    const int t4   = lane & 3;

    const int* inp  = inputs + b * L_;
    const int* adjb = adj + (size_t)b * (L_ * L_);

    // ---------------- phase 0: loads ----------------
    if (tid < 256) {   // atp[wd] = {pack(a0),pack(a1),pack(a2),pack(a3)} for word wd
        int wd = tid & 63, k = tid >> 6;
        const float* ap = (k == 0) ? a0p : (k == 1) ? a1p : (k == 2) ? a2p : a3p;
        ((unsigned*)(atp4 + wd))[k] = pack_bf16x2(ap[2 * wd], ap[2 * wd + 1]);
    }
    // embedding gather -> h f32 (tf32, swizzled) + hb bf16 (pair layout); rows 100..103 zero
    for (int e = tid; e < 104 * 32; e += 512) {
        int r = e >> 5, q = e & 31;
        float4 v = make_float4(0.f, 0.f, 0.f, 0.f);
        if (r < L_) {
            int id = inp[r];
            v = ((const float4*)(emb + (size_t)id * D_))[q];
            v.x = rna_tf32(v.x); v.y = rna_tf32(v.y);
            v.z = rna_tf32(v.z); v.w = rna_tf32(v.w);
        }
        *(float4*)(h_sm + HW(r, 4 * q)) = v;
        // pair layout: wd -> pos = (wd>>3)*8 + (wd&3)*2 + ((wd>>2)&1)
        int p0 = (q >> 2) * 8 + (q & 1) * 4 + ((q >> 1) & 1);
        hb_sm[r * HB + p0]     = pack_bf16x2(v.x, v.y);   // wd = 2q
        hb_sm[r * HB + p0 + 2] = pack_bf16x2(v.z, v.w);   // wd = 2q+1
    }
    // adj -> int8
    for (int e = tid; e < 2500; e += 512) {
        int i = e / 25, c = e % 25;
        int4 v = ((const int4*)(adjb + i * 100))[c];
        unsigned p = (unsigned)(v.x & 0xff) | ((unsigned)(v.y & 0xff) << 8)
                   | ((unsigned)(v.z & 0xff) << 16) | ((unsigned)(v.w & 0xff) << 24);
        *(unsigned*)(adj_sm + i * ADJS + c * 4) = p;
    }
    __syncthreads();

    // ---------- phase 1: GEMM1 (bf16 m16n8k16; all 4 edge types fused) ----------
    // jobs: 7 m16-tiles x 7 n16-pairs = 49; results staged in regs (bf16x2).
    unsigned stg[4][2][2];
    #pragma unroll
    for (int jj = 0; jj < 4; ++jj) {
        int job = w + jj * 16;
        if (job < 49) {
            int mt = job / 7, np = job % 7;
            int r0  = mt * 16;
            int jc0 = np * 16;
            const bool mguard = (mt == 6);
            const int  nnmax  = (np == 6) ? 1 : 2;

            float c[2][4][4];
            #pragma unroll
            for (int nn = 0; nn < 2; ++nn)
                #pragma unroll
                for (int k = 0; k < 4; ++k)
                    #pragma unroll
                    for (int r = 0; r < 4; ++r) c[nn][k][r] = 0.f;

            const unsigned* pa  = hb_sm + (r0 + g) * HB + 2 * t4;
            const unsigned* pb0 = hb_sm + (jc0 + g) * HB + 2 * t4;
            const unsigned* pb1 = hb_sm + (jc0 + 8 + g) * HB + 2 * t4;
            const uint4*    pt  = atp4 + t4;

            #pragma unroll
            for (int ks = 0; ks < 8; ++ks) {
                uint2 alo = *(const uint2*)(pa + ks * 8);
                uint2 ahi = mguard ? make_uint2(0u, 0u)
                                   : *(const uint2*)(pa + 8 * HB + ks * 8);
                uint4 ap0 = pt[ks * 8];
                uint4 ap1 = pt[ks * 8 + 4];
                {
                    uint2 bp = *(const uint2*)(pb0 + ks * 8);
                    mma_bf16(c[0][0], alo.x, ahi.x, alo.y, ahi.y, mulbf2(bp.x, ap0.x), mulbf2(bp.y, ap1.x));
                    mma_bf16(c[0][1], alo.x, ahi.x, alo.y, ahi.y, mulbf2(bp.x, ap0.y), mulbf2(bp.y, ap1.y));
                    mma_bf16(c[0][2], alo.x, ahi.x, alo.y, ahi.y, mulbf2(bp.x, ap0.z), mulbf2(bp.y, ap1.z));
                    mma_bf16(c[0][3], alo.x, ahi.x, alo.y, ahi.y, mulbf2(bp.x, ap0.w), mulbf2(bp.y, ap1.w));
                }
                if (nnmax == 2) {
                    uint2 bp = *(const uint2*)(pb1 + ks * 8);
                    mma_bf16(c[1][0], alo.x, ahi.x, alo.y, ahi.y, mulbf2(bp.x, ap0.x), mulbf2(bp.y, ap1.x));
                    mma_bf16(c[1][1], alo.x, ahi.x, alo.y, ahi.y, mulbf2(bp.x, ap0.y), mulbf2(bp.y, ap1.y));
                    mma_bf16(c[1][2], alo.x, ahi.x, alo.y, ahi.y, mulbf2(bp.x, ap0.z), mulbf2(bp.y, ap1.z));
                    mma_bf16(c[1][3], alo.x, ahi.x, alo.y, ahi.y, mulbf2(bp.x, ap0.w), mulbf2(bp.y, ap1.w));
                }
            }
            // select by adj + leaky-relu -> staged bf16x2
            #pragma unroll
            for (int nn = 0; nn < 2; ++nn) {
                #pragma unroll
                for (int hf = 0; hf < 2; ++hf) {
                    int row = r0 + g + hf * 8;
                    float v[2];
                    #pragma unroll
                    for (int e = 0; e < 2; ++e) {
                        int col = jc0 + nn * 8 + 2 * t4 + e;
                        int p = hf * 2 + e;
                        float val = NEG_INF_;
                        if (nn < nnmax && row < L_ && col < L_) {
                            int t = adj_sm[row * ADJS + col];
                            float x = (t == 1) ? c[nn][0][p] :
                                      (t == 2) ? c[nn][1][p] :
                                      (t == 3) ? c[nn][2][p] : c[nn][3][p];
                            x = (x > 0.f) ? x : 0.2f * x;
                            val = t ? x : NEG_INF_;
                        }
                        v[e] = val;
                    }
                    stg[jj][nn][hf] = pack_bf16x2(v[0], v[1]);
                }
            }
        }
    }
    __syncthreads();   // hb/atp/adj dead; al overlay becomes valid

    // write staged logits to al
    #pragma unroll
    for (int jj = 0; jj < 4; ++jj) {
        int job = w + jj * 16;
        if (job < 49) {
            int mt = job / 7, np = job % 7;
            int r0 = mt * 16, jc0 = np * 16;
            #pragma unroll
            for (int nn = 0; nn < 2; ++nn) {
                int col0 = jc0 + nn * 8 + 2 * t4;
                if (col0 < 104) {
                    #pragma unroll
                    for (int hf = 0; hf < 2; ++hf) {
                        int row = r0 + g + hf * 8;
                        if (row < 104) {
                            unsigned pk = stg[jj][nn][hf];
                            float2 vv = make_float2(__uint_as_float(pk << 16),
                                                    __uint_as_float(pk & 0xffff0000u));
                            *(float2*)(al_sm + row * AS + col0) = vv;
                        }
                    }
                }
            }
        }
    }
    __syncthreads();

    // ---------------- phase 2: softmax over j ----------------
    for (int i = w; i < L_; i += 16) {
        float x[4];
        #pragma unroll
        for (int q = 0; q < 4; ++q) {
            int j = lane + 32 * q;
            x[q] = (j < 104) ? al_sm[i * AS + j] : NEG_INF_;
        }
        float mx = fmaxf(fmaxf(x[0], x[1]), fmaxf(x[2], x[3]));
        #pragma unroll
        for (int o = 16; o > 0; o >>= 1) mx = fmaxf(mx, __shfl_xor_sync(0xffffffffu, mx, o));
        float ev[4], s = 0.f;
        #pragma unroll
        for (int q = 0; q < 4; ++q) {
            int j = lane + 32 * q;
            ev[q] = (j < L_) ? __expf(x[q] - mx) : 0.f;
            s += ev[q];
        }
        #pragma unroll
        for (int o = 16; o > 0; o >>= 1) s += __shfl_xor_sync(0xffffffffu, s, o);
        float inv = 1.f / s;
        #pragma unroll
        for (int q = 0; q < 4; ++q) {
            int j = lane + 32 * q;
            if (j < L_)       al_sm[i * AS + j] = rna_tf32(ev[q] * inv);
            else if (j < 104) al_sm[i * AS + j] = 0.f;
        }
    }
    // zero alpha rows 100..103 (GEMM2 K padding)
    for (int e = tid; e < 4 * AS; e += 512) al_sm[L_ * AS + e] = 0.f;
    __syncthreads();

    // ---------------- phase 3: GEMM2  out = alpha @ h  (tf32) ----------------
    {
        const int nA = (w & 7) * 2;
        const int ih = (w >> 3) * 2;
        float* outb = out + (size_t)b * (L_ * D_);
        #pragma unroll
        for (int ii = 0; ii < 2; ++ii) {
            int i32 = ih + ii;
            int nh2 = (i32 == 3) ? 1 : 2;
            int r0b = i32 * 32;
            float c2[2][2][4];
            #pragma unroll
            for (int nn = 0; nn < 2; ++nn)
                #pragma unroll
                for (int h = 0; h < 2; ++h)
                    #pragma unroll
                    for (int r = 0; r < 4; ++r) c2[nn][h][r] = 0.f;

            #pragma unroll
            for (int kt = 0; kt < 13; ++kt) {
                int col = kt * 8 + t4;
                unsigned A2[2][4];
                #pragma unroll
                for (int h = 0; h < 2; ++h) {
                    if (h < nh2) {
                        int r = r0b + h * 16 + g;
                        A2[h][0] = __float_as_uint(al_sm[r * AS + col]);
                        A2[h][1] = (i32 == 3) ? 0u : __float_as_uint(al_sm[(r + 8) * AS + col]);
                        A2[h][2] = __float_as_uint(al_sm[r * AS + col + 4]);
                        A2[h][3] = (i32 == 3) ? 0u : __float_as_uint(al_sm[(r + 8) * AS + col + 4]);
                    }
                }
                #pragma unroll
                for (int nn = 0; nn < 2; ++nn) {
                    int nt = nA + nn;
                    unsigned B0 = __float_as_uint(h_sm[HW(col, nt * 8 + g)]);
                    unsigned B1 = __float_as_uint(h_sm[HW(col + 4, nt * 8 + g)]);
                    mma_tf32(c2[nn][0], A2[0], B0, B1);
                    if (nh2 == 2) mma_tf32(c2[nn][1], A2[1], B0, B1);
                }
            }
            #pragma unroll
            for (int nn = 0; nn < 2; ++nn) {
                #pragma unroll
                for (int h = 0; h < 2; ++h) {
                    if (h < nh2) {
                        #pragma unroll
                        for (int p = 0; p < 2; ++p) {
                            int row = r0b + h * 16 + g + p * 8;
                            if (row < L_) {
                                int colo = (nA + nn) * 8 + t4 * 2;
                                float2 v2 = make_float2(c2[nn][h][p * 2], c2[nn][h][p * 2 + 1]);
                                *(float2*)(outb + row * D_ + colo) = v2;
                            }
                        }
                    }
                }
            }
        }
    }
}

extern "C" void kernel_launch(void* const* d_in, const int* in_sizes, int n_in,
                              void* d_out, int out_size) {
    // metadata order: inputs, adj, mask_item, item, emb_table, a0, a1, a2, a3
    const int*   inputs = (const int*)d_in[0];
    const int*   adj    = (const int*)d_in[1];
    const float* emb    = (const float*)d_in[4];
    const float* a0     = (const float*)d_in[5];
    const float* a1     = (const float*)d_in[6];
    const float* a2     = (const float*)d_in[7];
    const float* a3     = (const float*)d_in[8];
    float* out = (float*)d_out;

    cudaFuncSetAttribute(combine_graph_kernel,
                         cudaFuncAttributeMaxDynamicSharedMemorySize, SMEM_TOTAL);

    combine_graph_kernel<<<B_, 512, SMEM_TOTAL>>>(inputs, adj, emb, a0, a1, a2, a3, out);
}

// round 7
// speedup vs baseline: 2.1727x; 1.2732x over previous
#include <cuda_runtime.h>
#include <cuda_bf16.h>
#include <cstdint>
#include <cstddef>

// CombineGraph: h = emb[inputs]; e_k = leakyrelu(einsum(bid,bjd,d->bij; h,h,a_k));
// alpha = softmax(select_by_adj(e_k, -9e15)); out = alpha @ h.
// B=512, L=100, D=128. One CTA/batch, 2 CTA/SM (R4 structure).
// GEMM1: bf16 m16n8k16, fragments via ldmatrix (A x4, B x2), B scaled by packed a_k.
// GEMM2: tf32 mma.sync with XOR-swizzled h (conflict-free B loads).

#define B_    512
#define L_    100
#define D_    128
#define HB    68         // hb row stride (u32 words): 68 mod 32 = 4 -> ldmatrix conflict-free
#define AS    108        // alpha row stride (floats)
#define ADJS  112        // adj row stride (bytes)
#define NEG_INF_ -9e15f

// ---- smem byte offsets ----
#define OFF_H    0            // h f32 swizzled: 104*128*4 = 53248
#define OFF_HB   53248        // h bf16: 104*68*4 = 28288
#define OFF_ATP  81536        // a packed uint4[64] = 1024
#define OFF_ADJ  82560        // adj int8: 100*112 = 11200 (end 93760)
#define OFF_AL   53248        // alpha overlays hb/atp/adj: 104*108*4 = 44928 (end 98176)
#define SMEM_TOTAL 98176

// h f32 swizzle: conflict-free for STS.128 write and GEMM2 B-fragment read
#define HW(r, c) ((r) * 128 + ((c) ^ (((r) & 3) << 3)))

__device__ __forceinline__ uint32_t smem_u32(const void* p) {
    uint32_t a;
    asm("{ .reg .u64 t; cvta.to.shared.u64 t, %1; cvt.u32.u64 %0, t; }" : "=r"(a) : "l"(p));
    return a;
}
__device__ __forceinline__ float rna_tf32(float x) {
    unsigned u; asm("cvt.rna.tf32.f32 %0, %1;" : "=r"(u) : "f"(x));
    return __uint_as_float(u);
}
__device__ __forceinline__ unsigned pack_bf16x2(float lo, float hi) {
    unsigned r; asm("cvt.rn.satfinite.bf16x2.f32 %0, %1, %2;" : "=r"(r) : "f"(hi), "f"(lo));
    return r;
}
__device__ __forceinline__ unsigned mulbf2(unsigned a, unsigned b) {
    unsigned r; asm("mul.bf16x2 %0, %1, %2;" : "=r"(r) : "r"(a), "r"(b));
    return r;
}
__device__ __forceinline__ void ldsm_x4(unsigned& r0, unsigned& r1, unsigned& r2, unsigned& r3,
                                        uint32_t addr) {
    asm volatile("ldmatrix.sync.aligned.m8n8.x4.shared.b16 {%0,%1,%2,%3}, [%4];"
                 : "=r"(r0), "=r"(r1), "=r"(r2), "=r"(r3) : "r"(addr));
}
__device__ __forceinline__ void ldsm_x2(unsigned& r0, unsigned& r1, uint32_t addr) {
    asm volatile("ldmatrix.sync.aligned.m8n8.x2.shared.b16 {%0,%1}, [%2];"
                 : "=r"(r0), "=r"(r1) : "r"(addr));
}
__device__ __forceinline__ void mma_bf16(float* c, unsigned a0, unsigned a1,
                                         unsigned a2, unsigned a3,
                                         unsigned b0, unsigned b1) {
    asm volatile(
        "mma.sync.aligned.m16n8k16.row.col.f32.bf16.bf16.f32 "
        "{%0,%1,%2,%3},{%4,%5,%6,%7},{%8,%9},{%0,%1,%2,%3};\n"
        : "+f"(c[0]), "+f"(c[1]), "+f"(c[2]), "+f"(c[3])
        : "r"(a0), "r"(a1), "r"(a2), "r"(a3), "r"(b0), "r"(b1));
}
__device__ __forceinline__ void mma_tf32(float* c, const unsigned* a, unsigned b0, unsigned b1) {
    asm volatile(
        "mma.sync.aligned.m16n8k8.row.col.f32.tf32.tf32.f32 "
        "{%0,%1,%2,%3},{%4,%5,%6,%7},{%8,%9},{%0,%1,%2,%3};\n"
        : "+f"(c[0]), "+f"(c[1]), "+f"(c[2]), "+f"(c[3])
        : "r"(a[0]), "r"(a[1]), "r"(a[2]), "r"(a[3]), "r"(b0), "r"(b1));
}

__global__ __launch_bounds__(512, 2)
void combine_graph_kernel(const int* __restrict__ inputs,
                          const int* __restrict__ adj,
                          const float* __restrict__ emb,
                          const float* __restrict__ a0p,
                          const float* __restrict__ a1p,
                          const float* __restrict__ a2p,
                          const float* __restrict__ a3p,
                          float* __restrict__ out)
{
    extern __shared__ char smem[];
    float*    h_sm   = (float*)(smem + OFF_H);
    unsigned* hb_sm  = (unsigned*)(smem + OFF_HB);
    uint4*    atp4   = (uint4*)(smem + OFF_ATP);
    char*     adj_sm = smem + OFF_ADJ;
    float*    al_sm  = (float*)(smem + OFF_AL);   // overlays hb/atp/adj after GEMM1
    const uint32_t hb_u32 = smem_u32(hb_sm);

    const int b    = blockIdx.x;
    const int tid  = threadIdx.x;
    const int w    = tid >> 5;
    const int lane = tid & 31;
    const int g    = lane >> 2;
    const int t4   = lane & 3;

    const int* inp  = inputs + b * L_;
    const int* adjb = adj + (size_t)b * (L_ * L_);

    // ---------------- phase 0: loads ----------------
    if (tid < 256) {   // atp[wd] = {pack(a0),pack(a1),pack(a2),pack(a3)} for word wd
        int wd = tid & 63, k = tid >> 6;
        const float* ap = (k == 0) ? a0p : (k == 1) ? a1p : (k == 2) ? a2p : a3p;
        ((unsigned*)(atp4 + wd))[k] = pack_bf16x2(ap[2 * wd], ap[2 * wd + 1]);
    }
    // embedding gather -> h f32 (tf32, swizzled) + hb bf16; rows 100..103 zero
    for (int e = tid; e < 104 * 32; e += 512) {
        int r = e >> 5, q = e & 31;
        float4 v = make_float4(0.f, 0.f, 0.f, 0.f);
        if (r < L_) {
            int id = inp[r];
            v = ((const float4*)(emb + (size_t)id * D_))[q];
            v.x = rna_tf32(v.x); v.y = rna_tf32(v.y);
            v.z = rna_tf32(v.z); v.w = rna_tf32(v.w);
        }
        *(float4*)(h_sm + HW(r, 4 * q)) = v;
        uint2 p2 = make_uint2(pack_bf16x2(v.x, v.y), pack_bf16x2(v.z, v.w));
        *(uint2*)(hb_sm + r * HB + 2 * q) = p2;
    }
    // adj -> int8
    for (int e = tid; e < 2500; e += 512) {
        int i = e / 25, c = e % 25;
        int4 v = ((const int4*)(adjb + i * 100))[c];
        unsigned p = (unsigned)(v.x & 0xff) | ((unsigned)(v.y & 0xff) << 8)
                   | ((unsigned)(v.z & 0xff) << 16) | ((unsigned)(v.w & 0xff) << 24);
        *(unsigned*)(adj_sm + i * ADJS + c * 4) = p;
    }
    __syncthreads();

    // ---------- phase 1: GEMM1 (bf16 m16n8k16 via ldmatrix; 4 edge types fused) ----------
    // jobs: 7 m16-tiles x 7 n16-pairs = 49; results staged in regs (bf16x2).
    unsigned stg[4][2][2];
    #pragma unroll
    for (int jj = 0; jj < 4; ++jj) {
        int job = w + jj * 16;
        if (job < 49) {
            int mt = job / 7, np = job % 7;
            int r0  = mt * 16;
            int jc0 = np * 16;
            const int nnmax = (np == 6) ? 1 : 2;

            float c[2][4][4];
            #pragma unroll
            for (int nn = 0; nn < 2; ++nn)
                #pragma unroll
                for (int k = 0; k < 4; ++k)
                    #pragma unroll
                    for (int r = 0; r < 4; ++r) c[nn][k][r] = 0.f;

            // ldmatrix addresses
            int row_a = r0 + (lane & 15);
            if (row_a > 103) row_a = 103;            // mt==6: clamp to zero rows
            uint32_t a_addr  = hb_u32 + (uint32_t)(row_a * HB + ((lane >> 4) << 2)) * 4u;
            int row_b = jc0 + (lane & 7);
            uint32_t b_addr0 = hb_u32 + (uint32_t)(row_b * HB + (((lane >> 3) & 1) << 2)) * 4u;
            uint32_t b_addr1 = b_addr0 + (uint32_t)(8 * HB * 4);
            const uint4* pt = atp4 + t4;

            #pragma unroll 2
            for (int ks = 0; ks < 8; ++ks) {
                unsigned A0, A1, A2, A3;
                ldsm_x4(A0, A1, A2, A3, a_addr + ks * 32u);
                uint4 ap0 = pt[ks * 8];
                uint4 ap1 = pt[ks * 8 + 4];
                {
                    unsigned B0, B1;
                    ldsm_x2(B0, B1, b_addr0 + ks * 32u);
                    mma_bf16(c[0][0], A0, A1, A2, A3, mulbf2(B0, ap0.x), mulbf2(B1, ap1.x));
                    mma_bf16(c[0][1], A0, A1, A2, A3, mulbf2(B0, ap0.y), mulbf2(B1, ap1.y));
                    mma_bf16(c[0][2], A0, A1, A2, A3, mulbf2(B0, ap0.z), mulbf2(B1, ap1.z));
                    mma_bf16(c[0][3], A0, A1, A2, A3, mulbf2(B0, ap0.w), mulbf2(B1, ap1.w));
                }
                if (nnmax == 2) {
                    unsigned B0, B1;
                    ldsm_x2(B0, B1, b_addr1 + ks * 32u);
                    mma_bf16(c[1][0], A0, A1, A2, A3, mulbf2(B0, ap0.x), mulbf2(B1, ap1.x));
                    mma_bf16(c[1][1], A0, A1, A2, A3, mulbf2(B0, ap0.y), mulbf2(B1, ap1.y));
                    mma_bf16(c[1][2], A0, A1, A2, A3, mulbf2(B0, ap0.z), mulbf2(B1, ap1.z));
                    mma_bf16(c[1][3], A0, A1, A2, A3, mulbf2(B0, ap0.w), mulbf2(B1, ap1.w));
                }
            }
            // select by adj + leaky-relu -> staged bf16x2
            #pragma unroll
            for (int nn = 0; nn < 2; ++nn) {
                #pragma unroll
                for (int hf = 0; hf < 2; ++hf) {
                    int row = r0 + g + hf * 8;
                    float v[2];
                    #pragma unroll
                    for (int e = 0; e < 2; ++e) {
                        int col = jc0 + nn * 8 + 2 * t4 + e;
                        int p = hf * 2 + e;
                        float val = NEG_INF_;
                        if (nn < nnmax && row < L_ && col < L_) {
                            int t = adj_sm[row * ADJS + col];
                            float x = (t == 1) ? c[nn][0][p] :
                                      (t == 2) ? c[nn][1][p] :
                                      (t == 3) ? c[nn][2][p] : c[nn][3][p];
                            x = (x > 0.f) ? x : 0.2f * x;
                            val = t ? x : NEG_INF_;
                        }
                        v[e] = val;
                    }
                    stg[jj][nn][hf] = pack_bf16x2(v[0], v[1]);
                }
            }
        }
    }
    __syncthreads();   // hb/atp/adj dead; al overlay becomes valid

    // write staged logits to al
    #pragma unroll
    for (int jj = 0; jj < 4; ++jj) {
        int job = w + jj * 16;
        if (job < 49) {
            int mt = job / 7, np = job % 7;
            int r0 = mt * 16, jc0 = np * 16;
            #pragma unroll
            for (int nn = 0; nn < 2; ++nn) {
                int col0 = jc0 + nn * 8 + 2 * t4;
                if (col0 < 104) {
                    #pragma unroll
                    for (int hf = 0; hf < 2; ++hf) {
                        int row = r0 + g + hf * 8;
                        if (row < 104) {
                            unsigned pk = stg[jj][nn][hf];
                            float2 vv = make_float2(__uint_as_float(pk << 16),
                                                    __uint_as_float(pk & 0xffff0000u));
                            *(float2*)(al_sm + row * AS + col0) = vv;
                        }
                    }
                }
            }
        }
    }
    __syncthreads();

    // ---------------- phase 2: softmax over j ----------------
    for (int i = w; i < L_; i += 16) {
        float x[4];
        #pragma unroll
        for (int q = 0; q < 4; ++q) {
            int j = lane + 32 * q;
            x[q] = (j < 104) ? al_sm[i * AS + j] : NEG_INF_;
        }
        float mx = fmaxf(fmaxf(x[0], x[1]), fmaxf(x[2], x[3]));
        #pragma unroll
        for (int o = 16; o > 0; o >>= 1) mx = fmaxf(mx, __shfl_xor_sync(0xffffffffu, mx, o));
        float ev[4], s = 0.f;
        #pragma unroll
        for (int q = 0; q < 4; ++q) {
            int j = lane + 32 * q;
            ev[q] = (j < L_) ? __expf(x[q] - mx) : 0.f;
            s += ev[q];
        }
        #pragma unroll
        for (int o = 16; o > 0; o >>= 1) s += __shfl_xor_sync(0xffffffffu, s, o);
        float inv = 1.f / s;
        #pragma unroll
        for (int q = 0; q < 4; ++q) {
            int j = lane + 32 * q;
            if (j < L_)       al_sm[i * AS + j] = rna_tf32(ev[q] * inv);
            else if (j < 104) al_sm[i * AS + j] = 0.f;
        }
    }
    // zero alpha rows 100..103 (GEMM2 K padding)
    for (int e = tid; e < 4 * AS; e += 512) al_sm[L_ * AS + e] = 0.f;
    __syncthreads();

    // ---------------- phase 3: GEMM2  out = alpha @ h  (tf32) ----------------
    {
        const int nA = (w & 7) * 2;
        const int ih = (w >> 3) * 2;
        float* outb = out + (size_t)b * (L_ * D_);
        #pragma unroll
        for (int ii = 0; ii < 2; ++ii) {
            int i32 = ih + ii;
            int nh2 = (i32 == 3) ? 1 : 2;
            int r0b = i32 * 32;
            float c2[2][2][4];
            #pragma unroll
            for (int nn = 0; nn < 2; ++nn)
                #pragma unroll
                for (int h = 0; h < 2; ++h)
                    #pragma unroll
                    for (int r = 0; r < 4; ++r) c2[nn][h][r] = 0.f;

            #pragma unroll 4
            for (int kt = 0; kt < 13; ++kt) {
                int col = kt * 8 + t4;
                unsigned A2[2][4];
                #pragma unroll
                for (int h = 0; h < 2; ++h) {
                    if (h < nh2) {
                        int r = r0b + h * 16 + g;
                        A2[h][0] = __float_as_uint(al_sm[r * AS + col]);
                        A2[h][1] = (i32 == 3) ? 0u : __float_as_uint(al_sm[(r + 8) * AS + col]);
                        A2[h][2] = __float_as_uint(al_sm[r * AS + col + 4]);
                        A2[h][3] = (i32 == 3) ? 0u : __float_as_uint(al_sm[(r + 8) * AS + col + 4]);
                    }
                }
                #pragma unroll
                for (int nn = 0; nn < 2; ++nn) {
                    int nt = nA + nn;
                    unsigned B0 = __float_as_uint(h_sm[HW(col, nt * 8 + g)]);
                    unsigned B1 = __float_as_uint(h_sm[HW(col + 4, nt * 8 + g)]);
                    mma_tf32(c2[nn][0], A2[0], B0, B1);
                    if (nh2 == 2) mma_tf32(c2[nn][1], A2[1], B0, B1);
                }
            }
            #pragma unroll
            for (int nn = 0; nn < 2; ++nn) {
                #pragma unroll
                for (int h = 0; h < 2; ++h) {
                    if (h < nh2) {
                        #pragma unroll
                        for (int p = 0; p < 2; ++p) {
                            int row = r0b + h * 16 + g + p * 8;
                            if (row < L_) {
                                int colo = (nA + nn) * 8 + t4 * 2;
                                float2 v2 = make_float2(c2[nn][h][p * 2], c2[nn][h][p * 2 + 1]);
                                *(float2*)(outb + row * D_ + colo) = v2;
                            }
                        }
                    }
                }
            }
        }
    }
}

extern "C" void kernel_launch(void* const* d_in, const int* in_sizes, int n_in,
                              void* d_out, int out_size) {
    // metadata order: inputs, adj, mask_item, item, emb_table, a0, a1, a2, a3
    const int*   inputs = (const int*)d_in[0];
    const int*   adj    = (const int*)d_in[1];
    const float* emb    = (const float*)d_in[4];
    const float* a0     = (const float*)d_in[5];
    const float* a1     = (const float*)d_in[6];
    const float* a2     = (const float*)d_in[7];
    const float* a3     = (const float*)d_in[8];
    float* out = (float*)d_out;

    cudaFuncSetAttribute(combine_graph_kernel,
                         cudaFuncAttributeMaxDynamicSharedMemorySize, SMEM_TOTAL);

    combine_graph_kernel<<<B_, 512, SMEM_TOTAL>>>(inputs, adj, emb, a0, a1, a2, a3, out);
}